// round 3
// baseline (speedup 1.0000x reference)
#include <cuda_runtime.h>
#include <stdint.h>

#define USER_NUM 100000
#define ITEM_NUM 200000
#define NNODES   (USER_NUM + ITEM_NUM)   // 300000
#define EMB      64
#define TOT      (NNODES * EMB)
#define MAXE     2097152                 // >= 1,250,000 edges

#define SCAN_TPB 1024
#define NSCANBLK ((NNODES + SCAN_TPB - 1) / SCAN_TPB)   // 293

// ---- static scratch (no cudaMalloc allowed) ----
__device__ int   g_counts[NNODES];         // histogram, then reused as fill cursor
__device__ int   g_offsets[NNODES + 1];
__device__ int   g_blocksums[512];
__device__ int2  g_csr_cv[MAXE];           // packed (col, val-as-bits)
__device__ float g_bufA[TOT];              // e1 / e2 ping-pong
__device__ float g_bufB[TOT];

// ---------------------------------------------------------------------------
__global__ void zero_counts_kernel(int* __restrict__ counts) {
    int i = blockIdx.x * blockDim.x + threadIdx.x;
    if (i < NNODES) counts[i] = 0;
}

__global__ void hist_kernel(const int* __restrict__ rows, int* __restrict__ counts, int n) {
    int i = blockIdx.x * blockDim.x + threadIdx.x;
    if (i < n) atomicAdd(&counts[rows[i]], 1);
}

// block-local exclusive scan; emits block totals; zeroes counts (freeing it as cursor)
__global__ void scan1_kernel(int* __restrict__ counts, int* __restrict__ offsets,
                             int* __restrict__ blocksums) {
    __shared__ int sh[SCAN_TPB];
    int tid = threadIdx.x;
    int gid = blockIdx.x * SCAN_TPB + tid;
    int v = (gid < NNODES) ? counts[gid] : 0;
    sh[tid] = v;
    __syncthreads();
    for (int off = 1; off < SCAN_TPB; off <<= 1) {
        int t = (tid >= off) ? sh[tid - off] : 0;
        __syncthreads();
        sh[tid] += t;
        __syncthreads();
    }
    if (gid < NNODES) {
        offsets[gid] = sh[tid] - v;   // exclusive within block
        counts[gid]  = 0;             // becomes fill cursor
    }
    if (tid == SCAN_TPB - 1) blocksums[blockIdx.x] = sh[tid];
}

// single block: exclusive scan of block totals (NSCANBLK <= 512)
__global__ void scan2_kernel(int* __restrict__ blocksums, int nblk) {
    __shared__ int sh[512];
    int tid = threadIdx.x;
    int v = (tid < nblk) ? blocksums[tid] : 0;
    sh[tid] = v;
    __syncthreads();
    for (int off = 1; off < 512; off <<= 1) {
        int t = (tid >= off) ? sh[tid - off] : 0;
        __syncthreads();
        sh[tid] += t;
        __syncthreads();
    }
    if (tid < nblk) blocksums[tid] = sh[tid] - v;
}

__global__ void scan3_kernel(int* __restrict__ offsets, const int* __restrict__ blocksums,
                             int n_edges) {
    int gid = blockIdx.x * SCAN_TPB + threadIdx.x;
    if (gid < NNODES) offsets[gid] += blocksums[blockIdx.x];
    if (gid == 0) offsets[NNODES] = n_edges;
}

__global__ void fill_kernel(const int* __restrict__ rows, const int* __restrict__ cols,
                            const float* __restrict__ vals,
                            const int* __restrict__ offsets, int* __restrict__ cursor,
                            int2* __restrict__ csr_cv, int n) {
    int e = blockIdx.x * blockDim.x + threadIdx.x;
    if (e >= n) return;
    int r = rows[e];
    int pos = offsets[r] + atomicAdd(&cursor[r], 1);
    csr_cv[pos] = make_int2(cols[e], __float_as_int(vals[e]));
}

// ---------------------------------------------------------------------------
// CSR SpMM: 16 lanes per row, one float4 per lane. Edge loop unrolled x4 with
// batched independent gathers (MLP=4/lane). Fused epilogues:
//   MODE 0: next = s;  acc = ego(r) + s     (gather from ego = user||item)
//   MODE 1: next = s;  acc += s
//   MODE 2:            acc = (acc + s) * 0.25
// ---------------------------------------------------------------------------
template <int MODE>
__device__ __forceinline__ const float4* gsrc(int c, const float4* x,
                                              const float4* user, const float4* item) {
    if (MODE == 0)
        return (c < USER_NUM) ? (user + (long long)c * 16)
                              : (item + (long long)(c - USER_NUM) * 16);
    return x + (long long)c * 16;
}

template <int MODE>
__global__ __launch_bounds__(256) void spmm_csr_kernel(
        const int*  __restrict__ offsets,
        const int2* __restrict__ cv,
        const float4* __restrict__ x,
        const float4* __restrict__ user,
        const float4* __restrict__ item,
        float4* __restrict__ next,
        float4* __restrict__ acc) {
    int t = blockIdx.x * blockDim.x + threadIdx.x;
    int r = t >> 4;
    int l = t & 15;
    if (r >= NNODES) return;

    int s = __ldg(offsets + r);
    int e = __ldg(offsets + r + 1);

    float4 a = make_float4(0.f, 0.f, 0.f, 0.f);
    int i = s;
    for (; i + 4 <= e; i += 4) {
        int2 c0 = __ldg(cv + i);
        int2 c1 = __ldg(cv + i + 1);
        int2 c2 = __ldg(cv + i + 2);
        int2 c3 = __ldg(cv + i + 3);
        float4 x0 = __ldg(gsrc<MODE>(c0.x, x, user, item) + l);
        float4 x1 = __ldg(gsrc<MODE>(c1.x, x, user, item) + l);
        float4 x2 = __ldg(gsrc<MODE>(c2.x, x, user, item) + l);
        float4 x3 = __ldg(gsrc<MODE>(c3.x, x, user, item) + l);
        float v0 = __int_as_float(c0.y), v1 = __int_as_float(c1.y);
        float v2 = __int_as_float(c2.y), v3 = __int_as_float(c3.y);
        a.x += v0 * x0.x + v1 * x1.x + v2 * x2.x + v3 * x3.x;
        a.y += v0 * x0.y + v1 * x1.y + v2 * x2.y + v3 * x3.y;
        a.z += v0 * x0.z + v1 * x1.z + v2 * x2.z + v3 * x3.z;
        a.w += v0 * x0.w + v1 * x1.w + v2 * x2.w + v3 * x3.w;
    }
    // tail (0-3 edges), two at a time then one
    if (i + 2 <= e) {
        int2 c0 = __ldg(cv + i);
        int2 c1 = __ldg(cv + i + 1);
        float4 x0 = __ldg(gsrc<MODE>(c0.x, x, user, item) + l);
        float4 x1 = __ldg(gsrc<MODE>(c1.x, x, user, item) + l);
        float v0 = __int_as_float(c0.y), v1 = __int_as_float(c1.y);
        a.x += v0 * x0.x + v1 * x1.x;
        a.y += v0 * x0.y + v1 * x1.y;
        a.z += v0 * x0.z + v1 * x1.z;
        a.w += v0 * x0.w + v1 * x1.w;
        i += 2;
    }
    if (i < e) {
        int2 c0 = __ldg(cv + i);
        float4 x0 = __ldg(gsrc<MODE>(c0.x, x, user, item) + l);
        float v0 = __int_as_float(c0.y);
        a.x += v0 * x0.x; a.y += v0 * x0.y; a.z += v0 * x0.z; a.w += v0 * x0.w;
    }

    long long idx = (long long)r * 16 + l;
    if (MODE == 0) {
        float4 ego = (r < USER_NUM) ? __ldg(&user[idx])
                                    : __ldg(&item[(long long)(r - USER_NUM) * 16 + l]);
        next[idx] = a;
        acc[idx]  = make_float4(ego.x + a.x, ego.y + a.y, ego.z + a.z, ego.w + a.w);
    } else if (MODE == 1) {
        next[idx] = a;
        float4 ac = acc[idx];
        acc[idx] = make_float4(ac.x + a.x, ac.y + a.y, ac.z + a.z, ac.w + a.w);
    } else {
        float4 ac = acc[idx];
        acc[idx] = make_float4((ac.x + a.x) * 0.25f, (ac.y + a.y) * 0.25f,
                               (ac.z + a.z) * 0.25f, (ac.w + a.w) * 0.25f);
    }
}

// ---------------------------------------------------------------------------
extern "C" void kernel_launch(void* const* d_in, const int* in_sizes, int n_in,
                              void* d_out, int out_size) {
    const float* user = (const float*)d_in[0];
    const float* item = (const float*)d_in[1];
    const float* vals = (const float*)d_in[2];
    const int*   rows = (const int*)  d_in[3];
    const int*   cols = (const int*)  d_in[4];
    const int n_edges = in_sizes[2];

    float* acc = (float*)d_out;

    int *counts, *offsets, *blocksums;
    int2 *csr_cv;
    float *A, *B;
    cudaGetSymbolAddress((void**)&counts,    g_counts);
    cudaGetSymbolAddress((void**)&offsets,   g_offsets);
    cudaGetSymbolAddress((void**)&blocksums, g_blocksums);
    cudaGetSymbolAddress((void**)&csr_cv,    g_csr_cv);
    cudaGetSymbolAddress((void**)&A,         g_bufA);
    cudaGetSymbolAddress((void**)&B,         g_bufB);

    const int TPB = 256;
    const int grid_nodes = (NNODES + TPB - 1) / TPB;
    const int grid_edges = (n_edges + TPB - 1) / TPB;
    const int grid_spmm  = (NNODES * 16 + TPB - 1) / TPB;

    // ---- CSR build (replayed in the graph; inputs are constant) ----
    zero_counts_kernel<<<grid_nodes, TPB>>>(counts);
    hist_kernel<<<grid_edges, TPB>>>(rows, counts, n_edges);
    scan1_kernel<<<NSCANBLK, SCAN_TPB>>>(counts, offsets, blocksums);
    scan2_kernel<<<1, 512>>>(blocksums, NSCANBLK);
    scan3_kernel<<<NSCANBLK, SCAN_TPB>>>(offsets, blocksums, n_edges);
    fill_kernel<<<grid_edges, TPB>>>(rows, cols, vals, offsets, counts,
                                     csr_cv, n_edges);

    // ---- 3 propagation layers, fully fused ----
    // layer 1: B = Adj*ego ; acc = ego + B
    spmm_csr_kernel<0><<<grid_spmm, TPB>>>(offsets, csr_cv, nullptr,
                                           (const float4*)user, (const float4*)item,
                                           (float4*)B, (float4*)acc);
    // layer 2: A = Adj*B ; acc += A
    spmm_csr_kernel<1><<<grid_spmm, TPB>>>(offsets, csr_cv, (const float4*)B,
                                           (const float4*)user, (const float4*)item,
                                           (float4*)A, (float4*)acc);
    // layer 3: acc = (acc + Adj*A) * 0.25
    spmm_csr_kernel<2><<<grid_spmm, TPB>>>(offsets, csr_cv, (const float4*)A,
                                           (const float4*)user, (const float4*)item,
                                           nullptr, (float4*)acc);
}

// round 4
// speedup vs baseline: 1.5107x; 1.5107x over previous
#include <cuda_runtime.h>
#include <cuda_fp16.h>
#include <stdint.h>

#define USER_NUM 100000
#define ITEM_NUM 200000
#define NNODES   (USER_NUM + ITEM_NUM)   // 300000
#define EMB      64
#define TOT      (NNODES * EMB)
#define MAXE     2097152                 // >= 1,250,000 edges

#define SCAN_TPB 1024
#define NSCANBLK ((NNODES + SCAN_TPB - 1) / SCAN_TPB)   // 293

// ---- static scratch (no cudaMalloc allowed) ----
__device__ int   g_counts[NNODES];
__device__ int   g_offsets[NNODES + 1];
__device__ int   g_blocksums[512];
__device__ int2  g_csr_cv[MAXE];           // packed (col, val-as-bits)
__device__ uint4 g_bufA[TOT / 8];          // fp16 e2  (row = 8 uint4 = 64 halfs)
__device__ uint4 g_bufB[TOT / 8];          // fp16 e1

// ---------------------------------------------------------------------------
__global__ void zero_counts_kernel(int* __restrict__ counts) {
    int i = blockIdx.x * blockDim.x + threadIdx.x;
    if (i < NNODES) counts[i] = 0;
}

__global__ void hist_kernel(const int* __restrict__ rows, int* __restrict__ counts, int n) {
    int i = blockIdx.x * blockDim.x + threadIdx.x;
    if (i < n) atomicAdd(&counts[rows[i]], 1);
}

__global__ void scan1_kernel(int* __restrict__ counts, int* __restrict__ offsets,
                             int* __restrict__ blocksums) {
    __shared__ int sh[SCAN_TPB];
    int tid = threadIdx.x;
    int gid = blockIdx.x * SCAN_TPB + tid;
    int v = (gid < NNODES) ? counts[gid] : 0;
    sh[tid] = v;
    __syncthreads();
    for (int off = 1; off < SCAN_TPB; off <<= 1) {
        int t = (tid >= off) ? sh[tid - off] : 0;
        __syncthreads();
        sh[tid] += t;
        __syncthreads();
    }
    if (gid < NNODES) {
        offsets[gid] = sh[tid] - v;
        counts[gid]  = 0;             // becomes fill cursor
    }
    if (tid == SCAN_TPB - 1) blocksums[blockIdx.x] = sh[tid];
}

__global__ void scan2_kernel(int* __restrict__ blocksums, int nblk) {
    __shared__ int sh[512];
    int tid = threadIdx.x;
    int v = (tid < nblk) ? blocksums[tid] : 0;
    sh[tid] = v;
    __syncthreads();
    for (int off = 1; off < 512; off <<= 1) {
        int t = (tid >= off) ? sh[tid - off] : 0;
        __syncthreads();
        sh[tid] += t;
        __syncthreads();
    }
    if (tid < nblk) blocksums[tid] = sh[tid] - v;
}

__global__ void scan3_kernel(int* __restrict__ offsets, const int* __restrict__ blocksums,
                             int n_edges) {
    int gid = blockIdx.x * SCAN_TPB + threadIdx.x;
    if (gid < NNODES) offsets[gid] += blocksums[blockIdx.x];
    if (gid == 0) offsets[NNODES] = n_edges;
}

__global__ void fill_kernel(const int* __restrict__ rows, const int* __restrict__ cols,
                            const float* __restrict__ vals,
                            const int* __restrict__ offsets, int* __restrict__ cursor,
                            int2* __restrict__ csr_cv, int n) {
    int e = blockIdx.x * blockDim.x + threadIdx.x;
    if (e >= n) return;
    int r = rows[e];
    int pos = offsets[r] + atomicAdd(&cursor[r], 1);
    csr_cv[pos] = make_int2(cols[e], __float_as_int(vals[e]));
}

// ---------------------------------------------------------------------------
// helpers: fp16x8 <-> fp32x8
__device__ __forceinline__ void unpack8(uint4 raw, float f[8]) {
    __half2 h0 = *reinterpret_cast<__half2*>(&raw.x);
    __half2 h1 = *reinterpret_cast<__half2*>(&raw.y);
    __half2 h2 = *reinterpret_cast<__half2*>(&raw.z);
    __half2 h3 = *reinterpret_cast<__half2*>(&raw.w);
    float2 f0 = __half22float2(h0), f1 = __half22float2(h1);
    float2 f2 = __half22float2(h2), f3 = __half22float2(h3);
    f[0]=f0.x; f[1]=f0.y; f[2]=f1.x; f[3]=f1.y;
    f[4]=f2.x; f[5]=f2.y; f[6]=f3.x; f[7]=f3.y;
}
__device__ __forceinline__ uint4 pack8(const float f[8]) {
    __half2 h0 = __float22half2_rn(make_float2(f[0], f[1]));
    __half2 h1 = __float22half2_rn(make_float2(f[2], f[3]));
    __half2 h2 = __float22half2_rn(make_float2(f[4], f[5]));
    __half2 h3 = __float22half2_rn(make_float2(f[6], f[7]));
    uint4 o;
    o.x = *reinterpret_cast<unsigned*>(&h0);
    o.y = *reinterpret_cast<unsigned*>(&h1);
    o.z = *reinterpret_cast<unsigned*>(&h2);
    o.w = *reinterpret_cast<unsigned*>(&h3);
    return o;
}

// ---------------------------------------------------------------------------
// CSR SpMM: 8 lanes per row, 8 floats per lane.
//   MODE 0: gather fp32 ego (user||item)  -> write fp16 next
//   MODE 1: gather fp16 x                 -> write fp16 next
//   MODE 2: gather fp16 x ; epilogue out = (ego + B + A + s) * 0.25  (fp32)
// ---------------------------------------------------------------------------
template <int MODE>
__global__ __launch_bounds__(256) void spmm_csr_kernel(
        const int*  __restrict__ offsets,
        const int2* __restrict__ cv,
        const uint4* __restrict__ xh,       // fp16 gather src (MODE 1/2)
        const float4* __restrict__ user,
        const float4* __restrict__ item,
        uint4* __restrict__ nexth,          // fp16 out (MODE 0/1)
        const uint4* __restrict__ bh,       // e1 (MODE 2)
        const uint4* __restrict__ ah,       // e2 (MODE 2)
        float4* __restrict__ out) {
    int t = blockIdx.x * blockDim.x + threadIdx.x;
    int r = t >> 3;
    int l = t & 7;
    if (r >= NNODES) return;

    int s = __ldg(offsets + r);
    int e = __ldg(offsets + r + 1);

    float a[8];
#pragma unroll
    for (int j = 0; j < 8; ++j) a[j] = 0.f;

    for (int i = s; i < e; ++i) {
        int2 c = __ldg(cv + i);
        float v = __int_as_float(c.y);
        if (MODE == 0) {
            const float4* src = (c.x < USER_NUM)
                ? (user + (size_t)c.x * 16 + l * 2)
                : (item + (size_t)(c.x - USER_NUM) * 16 + l * 2);
            float4 x0 = __ldg(src);
            float4 x1 = __ldg(src + 1);
            a[0] += v * x0.x; a[1] += v * x0.y; a[2] += v * x0.z; a[3] += v * x0.w;
            a[4] += v * x1.x; a[5] += v * x1.y; a[6] += v * x1.z; a[7] += v * x1.w;
        } else {
            uint4 raw = __ldg(xh + (size_t)c.x * 8 + l);
            float xf[8];
            unpack8(raw, xf);
#pragma unroll
            for (int j = 0; j < 8; ++j) a[j] += v * xf[j];
        }
    }

    if (MODE == 2) {
        size_t fo = (size_t)r * 16 + l * 2;   // float4 index into [N,64]
        float4 e0 = (r < USER_NUM)
            ? __ldg(&user[fo])
            : __ldg(&item[(size_t)(r - USER_NUM) * 16 + l * 2]);
        float4 e1 = (r < USER_NUM)
            ? __ldg(&user[fo + 1])
            : __ldg(&item[(size_t)(r - USER_NUM) * 16 + l * 2 + 1]);
        float bf[8], af[8];
        unpack8(__ldg(bh + (size_t)r * 8 + l), bf);
        unpack8(__ldg(ah + (size_t)r * 8 + l), af);
        float4 o0, o1;
        o0.x = (e0.x + bf[0] + af[0] + a[0]) * 0.25f;
        o0.y = (e0.y + bf[1] + af[1] + a[1]) * 0.25f;
        o0.z = (e0.z + bf[2] + af[2] + a[2]) * 0.25f;
        o0.w = (e0.w + bf[3] + af[3] + a[3]) * 0.25f;
        o1.x = (e1.x + bf[4] + af[4] + a[4]) * 0.25f;
        o1.y = (e1.y + bf[5] + af[5] + a[5]) * 0.25f;
        o1.z = (e1.z + bf[6] + af[6] + a[6]) * 0.25f;
        o1.w = (e1.w + bf[7] + af[7] + a[7]) * 0.25f;
        out[fo]     = o0;
        out[fo + 1] = o1;
    } else {
        nexth[(size_t)r * 8 + l] = pack8(a);
    }
}

// ---------------------------------------------------------------------------
extern "C" void kernel_launch(void* const* d_in, const int* in_sizes, int n_in,
                              void* d_out, int out_size) {
    const float* user = (const float*)d_in[0];
    const float* item = (const float*)d_in[1];
    const float* vals = (const float*)d_in[2];
    const int*   rows = (const int*)  d_in[3];
    const int*   cols = (const int*)  d_in[4];
    const int n_edges = in_sizes[2];

    float4* out = (float4*)d_out;

    int *counts, *offsets, *blocksums;
    int2 *csr_cv;
    uint4 *A, *B;
    cudaGetSymbolAddress((void**)&counts,    g_counts);
    cudaGetSymbolAddress((void**)&offsets,   g_offsets);
    cudaGetSymbolAddress((void**)&blocksums, g_blocksums);
    cudaGetSymbolAddress((void**)&csr_cv,    g_csr_cv);
    cudaGetSymbolAddress((void**)&A,         g_bufA);
    cudaGetSymbolAddress((void**)&B,         g_bufB);

    const int TPB = 256;
    const int grid_nodes = (NNODES + TPB - 1) / TPB;
    const int grid_edges = (n_edges + TPB - 1) / TPB;
    const int grid_spmm  = (NNODES * 8 + TPB - 1) / TPB;

    // ---- CSR build ----
    zero_counts_kernel<<<grid_nodes, TPB>>>(counts);
    hist_kernel<<<grid_edges, TPB>>>(rows, counts, n_edges);
    scan1_kernel<<<NSCANBLK, SCAN_TPB>>>(counts, offsets, blocksums);
    scan2_kernel<<<1, 512>>>(blocksums, NSCANBLK);
    scan3_kernel<<<NSCANBLK, SCAN_TPB>>>(offsets, blocksums, n_edges);
    fill_kernel<<<grid_edges, TPB>>>(rows, cols, vals, offsets, counts,
                                     csr_cv, n_edges);

    // ---- 3 propagation layers ----
    // layer 1: B = Adj*ego              (fp16 out, no acc traffic)
    spmm_csr_kernel<0><<<grid_spmm, TPB>>>(offsets, csr_cv, nullptr,
                                           (const float4*)user, (const float4*)item,
                                           B, nullptr, nullptr, nullptr);
    // layer 2: A = Adj*B                (fp16 in/out)
    spmm_csr_kernel<1><<<grid_spmm, TPB>>>(offsets, csr_cv, B,
                                           (const float4*)user, (const float4*)item,
                                           A, nullptr, nullptr, nullptr);
    // layer 3: out = (ego + B + A + Adj*A) * 0.25
    spmm_csr_kernel<2><<<grid_spmm, TPB>>>(offsets, csr_cv, A,
                                           (const float4*)user, (const float4*)item,
                                           nullptr, B, A, out);
}